// round 5
// baseline (speedup 1.0000x reference)
#include <cuda_runtime.h>
#include <cstdint>

// Problem constants
static constexpr int NB = 16;
static constexpr int NC = 256;
static constexpr int NH = 64;
static constexpr int NW = 64;
static constexpr int NP = 9;
static constexpr int DISP = 4;
static constexpr int PITCH = 384;      // smem row pitch (multiple of 128)
static constexpr int NTHREADS = 256;   // 8 warps -> perfectly balanced SMSPs

// ---- Type A: di = 0..7, i-tile = 4 rows ----
static constexpr int A_TI  = 4;
static constexpr int A_CH  = 8;
static constexpr int A_NST = NC / A_CH;           // 32 stages
static constexpr int A_YR  = A_TI + 7;            // r = ti+di in 0..10 -> 11 rows
static constexpr int A_XA  = A_CH * A_TI * PITCH;     // 12288
static constexpr int A_YA  = A_CH * A_YR * PITCH;     // 33792
static constexpr int A_BUF = A_XA + A_YA;             // 46080
static constexpr int A_STB = A_CH * NH * NW * 4;      // 131072
static constexpr int A_YROWS_TOT = A_CH * A_YR;       // 88

// ---- Type B: di = 8 only, i-tile = 32 rows ----
static constexpr int B_TI  = 32;
static constexpr int B_CH  = 2;
static constexpr int B_NST = NC / B_CH;           // 128 stages
static constexpr int B_XA  = B_CH * B_TI * PITCH;     // 24576
static constexpr int B_YA  = B_CH * B_TI * PITCH;     // 24576
static constexpr int B_BUF = B_XA + B_YA;             // 49152
static constexpr int B_STB = B_CH * NH * NW * 4;      // 32768

static constexpr int SMEM_TOTAL = 2 * B_BUF;          // 98304 (covers A's 92160)

__device__ __forceinline__ unsigned skew(int r) {
    return ((r & 1) << 4) + ((r & 2) << 5);
}
__device__ __forceinline__ void upk(unsigned long long v, float& lo, float& hi) {
    asm("mov.b64 {%0, %1}, %2;" : "=f"(lo), "=f"(hi) : "l"(v));
}
__device__ __forceinline__ unsigned long long pk(float lo, float hi) {
    unsigned long long r;
    asm("mov.b64 %0, {%1, %2};" : "=l"(r) : "f"(lo), "f"(hi));
    return r;
}
__device__ __forceinline__ void fma2(unsigned long long& acc,
                                     unsigned long long a, unsigned long long b) {
    asm("fma.rn.f32x2 %0, %1, %2, %0;" : "+l"(acc) : "l"(a), "l"(b));
}
__device__ __forceinline__ void lds2(unsigned addr,
                                     unsigned long long& a, unsigned long long& b) {
    asm volatile("ld.shared.v2.b64 {%0, %1}, [%2];"
                 : "=l"(a), "=l"(b) : "r"(addr));
}
__device__ __forceinline__ void cpa16(unsigned dst, const void* src) {
    asm volatile("cp.async.cg.shared.global [%0], [%1], 16;"
                 :: "r"(dst), "l"(src) : "memory");
}
__device__ __forceinline__ void commit() {
    asm volatile("cp.async.commit_group;" ::: "memory");
}
__device__ __forceinline__ void wait0() {
    asm volatile("cp.async.wait_group 0;" ::: "memory");
}

struct Acc {
    unsigned long long E[5][4];   // even dj: aligned col pairs
    unsigned long long O[4][3];   // odd dj: 3 mid pairs
    float sA[4], sB[4];           // odd dj scalar borders
};
__device__ __forceinline__ void acc_zero(Acc& a) {
#pragma unroll
    for (int e = 0; e < 5; ++e)
#pragma unroll
        for (int m = 0; m < 4; ++m) a.E[e][m] = 0ull;
#pragma unroll
    for (int o = 0; o < 4; ++o) {
#pragma unroll
        for (int m = 0; m < 3; ++m) a.O[o][m] = 0ull;
        a.sA[o] = 0.f; a.sB[o] = 0.f;
    }
}

// One channel's worth of math for one thread (8 cols x 9 dj).
__device__ __forceinline__ void chan(unsigned xp, unsigned yp, Acc& a) {
    unsigned long long X[4], W[8];
    lds2(xp,      X[0], X[1]);
    lds2(xp + 16, X[2], X[3]);
    lds2(yp,      W[0], W[1]);
    lds2(yp + 16, W[2], W[3]);
    lds2(yp + 32, W[4], W[5]);
    lds2(yp + 48, W[6], W[7]);

    float x0, x1, x2, x3, x4, x5, x6, x7;
    upk(X[0], x0, x1); upk(X[1], x2, x3);
    upk(X[2], x4, x5); upk(X[3], x6, x7);
    unsigned long long Sx[3] = {pk(x1, x2), pk(x3, x4), pk(x5, x6)};

#pragma unroll
    for (int e = 0; e < 5; ++e)
#pragma unroll
        for (int m = 0; m < 4; ++m)
            fma2(a.E[e][m], X[m], W[m + e]);

#pragma unroll
    for (int o = 0; o < 4; ++o) {
#pragma unroll
        for (int m = 0; m < 3; ++m)
            fma2(a.O[o][m], Sx[m], W[m + 1 + o]);
        float wl, wh, vl, vh;
        upk(W[o], wl, wh);
        upk(W[4 + o], vl, vh);
        a.sA[o] = fmaf(x0, wh, a.sA[o]);
        a.sB[o] = fmaf(x7, vl, a.sB[o]);
    }
}

__device__ __forceinline__ void epilogue(Acc& a, float* obase) {
    const float sc = 1.0f / (float)NC;
#pragma unroll
    for (int e = 0; e < 5; ++e) {
        float* op = obase + (size_t)(2 * e) * NH * NW;
        float4 v;
        upk(a.E[e][0], v.x, v.y); upk(a.E[e][1], v.z, v.w);
        v.x *= sc; v.y *= sc; v.z *= sc; v.w *= sc;
        *reinterpret_cast<float4*>(op) = v;
        upk(a.E[e][2], v.x, v.y); upk(a.E[e][3], v.z, v.w);
        v.x *= sc; v.y *= sc; v.z *= sc; v.w *= sc;
        *reinterpret_cast<float4*>(op + 4) = v;
    }
#pragma unroll
    for (int o = 0; o < 4; ++o) {
        float* op = obase + (size_t)(2 * o + 1) * NH * NW;
        float f1, f2, f3, f4, f5, f6;
        upk(a.O[o][0], f1, f2);
        upk(a.O[o][1], f3, f4);
        upk(a.O[o][2], f5, f6);
        float4 v;
        v.x = a.sA[o] * sc; v.y = f1 * sc; v.z = f2 * sc; v.w = f3 * sc;
        *reinterpret_cast<float4*>(op) = v;
        v.x = f4 * sc; v.y = f5 * sc; v.z = f6 * sc; v.w = a.sB[o] * sc;
        *reinterpret_cast<float4*>(op + 4) = v;
    }
}

__global__ void __launch_bounds__(NTHREADS, 2)
corr_kernel(const float* __restrict__ x, const float* __restrict__ y,
            float* __restrict__ out) {
    extern __shared__ char smem[];
    unsigned sm32;
    asm("{ .reg .u64 t; cvta.to.shared.u64 t, %1; cvt.u32.u64 %0, t; }"
        : "=r"(sm32) : "l"(smem));

    const int tid = threadIdx.x;
    const int bx  = blockIdx.x;

    if (bx < 256) {
        // ================= Type A: di = warp (0..7) =================
        const int di = tid >> 5;
        const int jg = (tid & 31) >> 2;
        const int ti = tid & 3;
        const int i0 = (bx & 15) * A_TI;
        const int b  = bx >> 4;

        for (int o = tid * 16; o < 2 * A_BUF; o += NTHREADS * 16)
            *reinterpret_cast<float4*>(smem + o) = make_float4(0.f, 0.f, 0.f, 0.f);

        // loader: tid<240, one 128B row-half each
        const char* src0 = reinterpret_cast<const char*>(x);
        unsigned dsto = 0;
        bool valid = false;
        if (tid < 240) {
            const int row = tid >> 1, half = tid & 1;
            if (row < A_YROWS_TOT) {                 // y rows
                const int cc = row / A_YR;
                const int rr = row - cc * A_YR;
                const int gy = i0 - DISP + rr;
                valid = ((unsigned)gy < (unsigned)NH);
                if (valid)
                    src0 = reinterpret_cast<const char*>(
                        y + (((size_t)(b * NC + cc) * NH + gy) * NW + half * 32));
                dsto = A_XA + cc * (A_YR * PITCH) + rr * PITCH + skew(rr)
                       + 16 + half * 128;
            } else {                                 // x rows
                const int j  = row - A_YROWS_TOT;
                const int cc = j >> 2;
                const int rr = j & 3;
                valid = true;
                src0 = reinterpret_cast<const char*>(
                    x + (((size_t)(b * NC + cc) * NH + (i0 + rr)) * NW + half * 32));
                dsto = cc * (A_TI * PITCH) + rr * PITCH + skew(rr) + half * 128;
            }
        }
        __syncthreads();

        auto issue = [&](int s) {
            if (valid) {
                const char* sp = src0 + (size_t)s * A_STB;
                const unsigned d = sm32 + (unsigned)((s & 1) * A_BUF) + dsto;
#pragma unroll
                for (int k = 0; k < 8; ++k) cpa16(d + k * 16, sp + k * 16);
            }
            commit();
        };
        issue(0);

        Acc a; acc_zero(a);
        const int r = ti + di;   // 0..10
        const unsigned xo = sm32 + (unsigned)(ti * PITCH) + skew(ti) + jg * 32;
        const unsigned yo = sm32 + (unsigned)A_XA + (unsigned)(r * PITCH)
                          + skew(r) + jg * 32;

        for (int s = 0; s < A_NST; ++s) {
            wait0();
            __syncthreads();
            if (s + 1 < A_NST) issue(s + 1);
            const unsigned bo = (unsigned)((s & 1) * A_BUF);
#pragma unroll 2
            for (int t = 0; t < A_CH; ++t) {
                const int cc = (t + di) & (A_CH - 1);   // stagger crossbar bursts
                chan(bo + (unsigned)(cc * (A_TI * PITCH)) + xo,
                     bo + (unsigned)(cc * (A_YR * PITCH)) + yo, a);
            }
        }

        epilogue(a, out + (((size_t)b * (NP * NP) + (size_t)di * NP) * NH
                           + (i0 + ti)) * NW + jg * 8);
    } else {
        // ================= Type B: di = 8 =================
        const int bz = bx - 256;
        const int i0 = (bz & 1) * B_TI;
        const int b  = bz >> 1;
        const int tb = tid >> 5;           // 0..7
        const int jg = (tid & 31) >> 2;
        const int tl = tid & 3;
        const int ti = tb * 4 + tl;        // 0..31

        for (int o = tid * 16; o < 2 * B_BUF; o += NTHREADS * 16)
            *reinterpret_cast<float4*>(smem + o) = make_float4(0.f, 0.f, 0.f, 0.f);

        const char* src0 = reinterpret_cast<const char*>(x);
        unsigned dsto = 0;
        bool valid = false;
        {
            const int row = tid >> 1, half = tid & 1;
            if (row < B_CH * B_TI) {                 // y rows (64)
                const int cc = row >> 5;
                const int rr = row & 31;
                const int gy = i0 + DISP + rr;       // di=8 => +4 shift
                valid = ((unsigned)gy < (unsigned)NH);
                if (valid)
                    src0 = reinterpret_cast<const char*>(
                        y + (((size_t)(b * NC + cc) * NH + gy) * NW + half * 32));
                dsto = B_XA + cc * (B_TI * PITCH) + rr * PITCH + skew(rr)
                       + 16 + half * 128;
            } else {                                 // x rows (64)
                const int rw = row - B_CH * B_TI;
                const int cc = rw >> 5;
                const int rr = rw & 31;
                valid = true;
                src0 = reinterpret_cast<const char*>(
                    x + (((size_t)(b * NC + cc) * NH + (i0 + rr)) * NW + half * 32));
                dsto = cc * (B_TI * PITCH) + rr * PITCH + skew(rr) + half * 128;
            }
        }
        __syncthreads();

        auto issueB = [&](int s) {
            if (valid) {
                const char* sp = src0 + (size_t)s * B_STB;
                const unsigned d = sm32 + (unsigned)((s & 1) * B_BUF) + dsto;
#pragma unroll
                for (int k = 0; k < 8; ++k) cpa16(d + k * 16, sp + k * 16);
            }
            commit();
        };
        issueB(0);

        Acc a; acc_zero(a);
        const unsigned xo = sm32 + (unsigned)(ti * PITCH) + skew(ti) + jg * 32;
        const unsigned yo = sm32 + (unsigned)B_XA + (unsigned)(ti * PITCH)
                          + skew(ti) + jg * 32;

        for (int s = 0; s < B_NST; ++s) {
            wait0();
            __syncthreads();
            if (s + 1 < B_NST) issueB(s + 1);
            const unsigned bo = (unsigned)((s & 1) * B_BUF);
#pragma unroll
            for (int t = 0; t < B_CH; ++t) {
                const int cc = (t + tb) & (B_CH - 1);
                chan(bo + (unsigned)(cc * (B_TI * PITCH)) + xo,
                     bo + (unsigned)(cc * (B_TI * PITCH)) + yo, a);
            }
        }

        epilogue(a, out + (((size_t)b * (NP * NP) + 8 * NP) * NH
                           + (i0 + ti)) * NW + jg * 8);
    }
}

extern "C" void kernel_launch(void* const* d_in, const int* in_sizes, int n_in,
                              void* d_out, int out_size) {
    const float* x = (const float*)d_in[0];
    const float* y = (const float*)d_in[1];
    float* out = (float*)d_out;
    (void)in_sizes; (void)n_in; (void)out_size;

    cudaFuncSetAttribute(corr_kernel,
                         cudaFuncAttributeMaxDynamicSharedMemorySize, SMEM_TOTAL);

    // 256 type-A blocks (di 0..7) + 32 type-B blocks (di=8) = 288 <= 296 capacity
    corr_kernel<<<288, NTHREADS, SMEM_TOTAL>>>(x, y, out);
}

// round 7
// speedup vs baseline: 1.0544x; 1.0544x over previous
#include <cuda_runtime.h>
#include <cstdint>

// Problem constants
static constexpr int NB = 16;
static constexpr int NC = 256;
static constexpr int NH = 64;
static constexpr int NW = 64;
static constexpr int NP = 9;
static constexpr int DISP = 4;

static constexpr int NTHREADS = 128;           // 4 warps -> perfect SMSP balance
static constexpr int CH_STRIDE16 = NH * NW / 4; // 1024 x 16B per channel

// Zero buffer for out-of-bounds rows/columns (device globals are zero-init).
__device__ __align__(16) float zbuf16[16];

__device__ __forceinline__ void upk(unsigned long long v, float& lo, float& hi) {
    asm("mov.b64 {%0, %1}, %2;" : "=f"(lo), "=f"(hi) : "l"(v));
}
__device__ __forceinline__ unsigned long long pk(float lo, float hi) {
    unsigned long long r;
    asm("mov.b64 %0, {%1, %2};" : "=l"(r) : "f"(lo), "f"(hi));
    return r;
}
// Packed dual fp32 FMA (Blackwell): 2x FFMA throughput vs scalar FFMA.
__device__ __forceinline__ void fma2(unsigned long long& acc,
                                     unsigned long long a, unsigned long long b) {
    asm("fma.rn.f32x2 %0, %1, %2, %0;" : "+l"(acc) : "l"(a), "l"(b));
}

struct Acc {
    unsigned long long E[5][4];   // even dj: aligned col pairs
    unsigned long long O[4][3];   // odd dj: 3 mid pairs
    float sA[4], sB[4];           // odd dj scalar borders
};

__global__ void __launch_bounds__(NTHREADS, 4)
corr_kernel(const float* __restrict__ x, const float* __restrict__ y,
            float* __restrict__ out) {
    const int tid  = threadIdx.x;
    const int wid  = tid >> 5;
    const int lane = tid & 31;
    const int jg   = lane >> 2;      // 0..7 : group of 8 output columns
    const int ti   = lane & 3;       // 0..3 : i-row inside 4-row tile
    const int bx   = blockIdx.x;

    int b, i0, di;
    if (bx < 512) {                  // di = 0..7 : warp picks one di
        const int g   = bx >> 8;     // 0 or 1
        const int rem = bx & 255;
        b  = rem >> 4;
        i0 = (rem & 15) * 4;
        di = g * 4 + wid;
    } else {                         // di = 8 : 4 warps cover 4 adjacent i-tiles
        const int bz = bx - 512;
        b  = bz >> 2;
        i0 = (bz & 3) * 16 + wid * 4;
        di = 8;
    }

    const int i  = i0 + ti;
    const int gy = i + di - DISP;                  // y row for this thread
    const bool rv = ((unsigned)gy < (unsigned)NH); // row in range?
    const int j0 = jg * 8;

    // x: 2x16B at cols j0..j0+7, always in-bounds.
    const ulonglong2* px = reinterpret_cast<const ulonglong2*>(
        x + (((size_t)b * NC) * NH + i) * NW + j0);

    // y window: 4x16B at cols j0-4 .. j0+11. Out-of-range loads -> zbuf, stride 0.
    const int gyc = rv ? gy : 0;
    const float* ybase = y + (((size_t)b * NC) * NH + gyc) * NW + (j0 - 4);
    const ulonglong2* zb = reinterpret_cast<const ulonglong2*>(zbuf16);
    const bool ok0 = rv && (jg != 0);
    const bool ok3 = rv && (jg != 7);
    const ulonglong2* pw0 = ok0 ? reinterpret_cast<const ulonglong2*>(ybase) + 0 : zb;
    const ulonglong2* pw1 = rv  ? reinterpret_cast<const ulonglong2*>(ybase) + 1 : zb;
    const ulonglong2* pw2 = rv  ? reinterpret_cast<const ulonglong2*>(ybase) + 2 : zb;
    const ulonglong2* pw3 = ok3 ? reinterpret_cast<const ulonglong2*>(ybase) + 3 : zb;
    const unsigned sw0 = ok0 ? CH_STRIDE16 : 0u;
    const unsigned sw1 = rv  ? CH_STRIDE16 : 0u;
    const unsigned sw2 = rv  ? CH_STRIDE16 : 0u;
    const unsigned sw3 = ok3 ? CH_STRIDE16 : 0u;

    Acc a;
#pragma unroll
    for (int e = 0; e < 5; ++e)
#pragma unroll
        for (int m = 0; m < 4; ++m) a.E[e][m] = 0ull;
#pragma unroll
    for (int o = 0; o < 4; ++o) {
#pragma unroll
        for (int m = 0; m < 3; ++m) a.O[o][m] = 0ull;
        a.sA[o] = 0.f; a.sB[o] = 0.f;
    }

#pragma unroll 2
    for (int c = 0; c < NC; ++c) {
        const ulonglong2 Xa = px[0];
        const ulonglong2 Xb = px[1];
        const ulonglong2 Wa = *pw0;
        const ulonglong2 Wb = *pw1;
        const ulonglong2 Wc = *pw2;
        const ulonglong2 Wd = *pw3;
        px  += CH_STRIDE16;
        pw0 += sw0; pw1 += sw1; pw2 += sw2; pw3 += sw3;

        unsigned long long X[4] = {Xa.x, Xa.y, Xb.x, Xb.y};
        unsigned long long W[8] = {Wa.x, Wa.y, Wb.x, Wb.y,
                                   Wc.x, Wc.y, Wd.x, Wd.y};

        float x0, x1, x2, x3, x4, x5, x6, x7;
        upk(X[0], x0, x1); upk(X[1], x2, x3);
        upk(X[2], x4, x5); upk(X[3], x6, x7);
        unsigned long long Sx[3] = {pk(x1, x2), pk(x3, x4), pk(x5, x6)};

        // Even dj: aligned x-pairs times aligned y-pairs.
#pragma unroll
        for (int e = 0; e < 5; ++e)
#pragma unroll
            for (int m = 0; m < 4; ++m)
                fma2(a.E[e][m], X[m], W[m + e]);

        // Odd dj: shifted x-pairs times aligned y-pairs + scalar borders.
#pragma unroll
        for (int o = 0; o < 4; ++o) {
#pragma unroll
            for (int m = 0; m < 3; ++m)
                fma2(a.O[o][m], Sx[m], W[m + 1 + o]);
            float wl, wh, vl, vh;
            upk(W[o], wl, wh);        // wh = y col j0 + 2o - 3
            upk(W[4 + o], vl, vh);    // vl = y col j0 + 4 + 2o
            a.sA[o] = fmaf(x0, wh, a.sA[o]);
            a.sB[o] = fmaf(x7, vl, a.sB[o]);
        }
    }

    // ---- epilogue: scale by 1/C and store ----
    const float sc = 1.0f / (float)NC;
    float* obase = out + (((size_t)b * (NP * NP) + (size_t)di * NP) * NH + i) * NW + j0;
#pragma unroll
    for (int e = 0; e < 5; ++e) {          // dj = 2e
        float* op = obase + (size_t)(2 * e) * NH * NW;
        float4 v;
        upk(a.E[e][0], v.x, v.y); upk(a.E[e][1], v.z, v.w);
        v.x *= sc; v.y *= sc; v.z *= sc; v.w *= sc;
        *reinterpret_cast<float4*>(op) = v;
        upk(a.E[e][2], v.x, v.y); upk(a.E[e][3], v.z, v.w);
        v.x *= sc; v.y *= sc; v.z *= sc; v.w *= sc;
        *reinterpret_cast<float4*>(op + 4) = v;
    }
#pragma unroll
    for (int o = 0; o < 4; ++o) {          // dj = 2o+1
        float* op = obase + (size_t)(2 * o + 1) * NH * NW;
        float f1, f2, f3, f4, f5, f6;
        upk(a.O[o][0], f1, f2);
        upk(a.O[o][1], f3, f4);
        upk(a.O[o][2], f5, f6);
        float4 v;
        v.x = a.sA[o] * sc; v.y = f1 * sc; v.z = f2 * sc; v.w = f3 * sc;
        *reinterpret_cast<float4*>(op) = v;
        v.x = f4 * sc; v.y = f5 * sc; v.z = f6 * sc; v.w = a.sB[o] * sc;
        *reinterpret_cast<float4*>(op + 4) = v;
    }
}

extern "C" void kernel_launch(void* const* d_in, const int* in_sizes, int n_in,
                              void* d_out, int out_size) {
    const float* x = (const float*)d_in[0];
    const float* y = (const float*)d_in[1];
    float* out = (float*)d_out;
    (void)in_sizes; (void)n_in; (void)out_size;

    // 512 blocks for di 0..7 (warp = di) + 64 blocks for di = 8 (warp = i-tile).
    // All 576 blocks have identical per-warp work: 256 channels x 72 accs.
    corr_kernel<<<576, NTHREADS>>>(x, y, out);
}

// round 8
// speedup vs baseline: 1.6268x; 1.5428x over previous
#include <cuda_runtime.h>
#include <cstdint>

// Problem constants
static constexpr int NB = 16;
static constexpr int NC = 256;
static constexpr int NH = 64;
static constexpr int NW = 64;
static constexpr int NP = 9;
static constexpr int DISP = 4;

// Tiling (identical to R4 best kernel)
static constexpr int TI = 4;
static constexpr int CH = 8;
static constexpr int NSTAGE = NC / CH;        // 32
static constexpr int YROWS = TI + 2 * DISP;   // 12
static constexpr int PITCH = 384;
static constexpr int XAREA = CH * TI * PITCH;     // 12288
static constexpr int YAREA = CH * YROWS * PITCH;  // 36864
static constexpr int BUF = XAREA + YAREA;         // 49152
static constexpr int NTHREADS = 288;              // 9 warps, warp = di
static constexpr int NROWS = CH * YROWS + CH * TI; // 96 y + 32 x = 128
static constexpr int STAGE_BYTES = CH * NH * NW * 4; // 131072
static constexpr int ROWB = NW * 4;               // 256B per bulk copy

// smem: [0..16) mbarriers full[2]; buffers at 128
static constexpr int BUF0 = 128;
static constexpr int SMEM_TOTAL = BUF0 + 2 * BUF; // 98432 -> 2 CTAs/SM

__device__ __forceinline__ unsigned skew(int r) {
    return ((r & 1) << 4) + ((r & 2) << 5);
}
__device__ __forceinline__ void upk(unsigned long long v, float& lo, float& hi) {
    asm("mov.b64 {%0, %1}, %2;" : "=f"(lo), "=f"(hi) : "l"(v));
}
__device__ __forceinline__ unsigned long long pk(float lo, float hi) {
    unsigned long long r;
    asm("mov.b64 %0, {%1, %2};" : "=l"(r) : "f"(lo), "f"(hi));
    return r;
}
__device__ __forceinline__ void fma2(unsigned long long& acc,
                                     unsigned long long a, unsigned long long b) {
    asm("fma.rn.f32x2 %0, %1, %2, %0;" : "+l"(acc) : "l"(a), "l"(b));
}
__device__ __forceinline__ void lds2(unsigned addr,
                                     unsigned long long& a, unsigned long long& b) {
    asm volatile("ld.shared.v2.b64 {%0, %1}, [%2];"
                 : "=l"(a), "=l"(b) : "r"(addr));
}
__device__ __forceinline__ void mbar_init(unsigned addr, unsigned count) {
    asm volatile("mbarrier.init.shared.b64 [%0], %1;" :: "r"(addr), "r"(count) : "memory");
}
__device__ __forceinline__ void mbar_expect(unsigned addr, unsigned bytes) {
    asm volatile("mbarrier.arrive.expect_tx.shared.b64 _, [%0], %1;"
                 :: "r"(addr), "r"(bytes) : "memory");
}
__device__ __forceinline__ void mbar_wait(unsigned addr, unsigned parity) {
    asm volatile(
        "{\n\t"
        ".reg .pred P;\n\t"
        "WL_%=:\n\t"
        "mbarrier.try_wait.parity.acquire.cta.shared::cta.b64 P, [%0], %1, 0x989680;\n\t"
        "@P bra.uni WD_%=;\n\t"
        "bra.uni WL_%=;\n\t"
        "WD_%=:\n\t"
        "}"
        :: "r"(addr), "r"(parity) : "memory");
}
__device__ __forceinline__ void bulk_g2s(unsigned dst, const void* src,
                                         unsigned bytes, unsigned mbar) {
    asm volatile(
        "cp.async.bulk.shared::cta.global.mbarrier::complete_tx::bytes "
        "[%0], [%1], %2, [%3];"
        :: "r"(dst), "l"(src), "r"(bytes), "r"(mbar) : "memory");
}

__global__ void __launch_bounds__(NTHREADS, 2)
corr_kernel(const float* __restrict__ x, const float* __restrict__ y,
            float* __restrict__ out) {
    extern __shared__ char smem[];
    unsigned sm32;
    asm("{ .reg .u64 t; cvta.to.shared.u64 t, %1; cvt.u32.u64 %0, t; }"
        : "=r"(sm32) : "l"(smem));

    const int tid  = threadIdx.x;
    const int di   = tid >> 5;       // warp = displacement row 0..8
    const int lane = tid & 31;
    const int jg   = lane >> 2;      // 8-col group
    const int ti   = lane & 3;       // i-row in tile
    const int i0   = blockIdx.x * TI;
    const int b    = blockIdx.y;

    // Zero both buffers (halo cols / OOB rows stay zero forever).
    for (int o = tid * 16; o < 2 * BUF; o += NTHREADS * 16)
        *reinterpret_cast<float4*>(smem + BUF0 + o) = make_float4(0.f, 0.f, 0.f, 0.f);

    if (tid == 0) {
        mbar_init(sm32 + 0, 1);   // full[0]
        mbar_init(sm32 + 8, 1);   // full[1]
    }
    __syncthreads();
    asm volatile("fence.proxy.async.shared::cta;" ::: "memory");

    // Per-block valid byte count (OOB y rows are skipped, never copied).
    const int lo = (4 - i0) > 0 ? (4 - i0) : 0;
    const int hi = (i0 - 56) > 0 ? (i0 - 56) : 0;
    const unsigned BYTES = (unsigned)((CH * (YROWS - lo - hi) + CH * TI) * ROWB);

    // Row-owner precompute: thread k < 128 owns row k (one 256B bulk per stage).
    const char* src0 = nullptr;
    unsigned dsto = 0;
    bool valid = false;
    if (tid < NROWS) {
        const int k = tid;
        if (k < CH * YROWS) {
            const int cc = k / YROWS;
            const int rr = k - cc * YROWS;
            const int gy = i0 - DISP + rr;
            valid = ((unsigned)gy < (unsigned)NH);
            if (valid)
                src0 = reinterpret_cast<const char*>(
                    y + (((size_t)(b * NC + cc) * NH + gy) * NW));
            dsto = XAREA + cc * (YROWS * PITCH) + rr * PITCH + skew(rr) + 16;
        } else {
            const int j  = k - CH * YROWS;
            const int cc = j >> 2;
            const int rr = j & 3;
            valid = true;
            src0 = reinterpret_cast<const char*>(
                x + (((size_t)(b * NC + cc) * NH + (i0 + rr)) * NW));
            dsto = cc * (TI * PITCH) + rr * PITCH + skew(rr);
        }
    }

    // Prologue: register expected bytes for stages 0 and 1, then issue them.
    if (tid == 0) {
        mbar_expect(sm32 + 0, BYTES);
        mbar_expect(sm32 + 8, BYTES);
    }
    __syncthreads();   // expects registered before any completion can land
    if (valid) {
        bulk_g2s(sm32 + BUF0 + dsto, src0, ROWB, sm32 + 0);
        bulk_g2s(sm32 + BUF0 + BUF + dsto, src0 + STAGE_BYTES, ROWB, sm32 + 8);
    }

    // Accumulators (R4 layout)
    unsigned long long accE[5][4], accO[4][3];
    float sA[4], sB[4];
#pragma unroll
    for (int e = 0; e < 5; ++e)
#pragma unroll
        for (int m = 0; m < 4; ++m) accE[e][m] = 0ull;
#pragma unroll
    for (int o = 0; o < 4; ++o) {
#pragma unroll
        for (int m = 0; m < 3; ++m) accO[o][m] = 0ull;
        sA[o] = 0.f; sB[o] = 0.f;
    }

    const int r = ti + di;   // y smem row 0..11
    const unsigned xoff = sm32 + BUF0 + (unsigned)(ti * PITCH) + skew(ti) + jg * 32;
    const unsigned yoff = sm32 + BUF0 + (unsigned)XAREA
                        + (unsigned)(r * PITCH) + skew(r) + jg * 32;

    for (int s = 0; s < NSTAGE; ++s) {
        const unsigned mb = sm32 + (unsigned)((s & 1) * 8);
        mbar_wait(mb, (unsigned)((s >> 1) & 1));
        if (tid == 0 && s + 2 < NSTAGE) mbar_expect(mb, BYTES);

        const unsigned bo = (unsigned)((s & 1) * BUF);
#pragma unroll 2
        for (int cc = 0; cc < CH; ++cc) {
            const unsigned xp = bo + (unsigned)(cc * (TI * PITCH)) + xoff;
            const unsigned yp = bo + (unsigned)(cc * (YROWS * PITCH)) + yoff;

            unsigned long long X[4], W[8];
            lds2(xp,      X[0], X[1]);
            lds2(xp + 16, X[2], X[3]);
            lds2(yp,      W[0], W[1]);
            lds2(yp + 16, W[2], W[3]);
            lds2(yp + 32, W[4], W[5]);
            lds2(yp + 48, W[6], W[7]);

            float x0, x1, x2, x3, x4, x5, x6, x7;
            upk(X[0], x0, x1); upk(X[1], x2, x3);
            upk(X[2], x4, x5); upk(X[3], x6, x7);
            unsigned long long Sx[3] = {pk(x1, x2), pk(x3, x4), pk(x5, x6)};

#pragma unroll
            for (int e = 0; e < 5; ++e)
#pragma unroll
                for (int m = 0; m < 4; ++m)
                    fma2(accE[e][m], X[m], W[m + e]);

#pragma unroll
            for (int o = 0; o < 4; ++o) {
#pragma unroll
                for (int m = 0; m < 3; ++m)
                    fma2(accO[o][m], Sx[m], W[m + 1 + o]);
                float wl, wh, vl, vh;
                upk(W[o], wl, wh);
                upk(W[4 + o], vl, vh);
                sA[o] = fmaf(x0, wh, sA[o]);
                sB[o] = fmaf(x7, vl, sB[o]);
            }
        }

        __syncthreads();   // everyone finished reading buffer (s&1)
        if (valid && s + 2 < NSTAGE) {
            bulk_g2s(sm32 + BUF0 + (unsigned)((s & 1) * BUF) + dsto,
                     src0 + (size_t)(s + 2) * STAGE_BYTES, ROWB, mb);
        }
    }

    // ---- epilogue: scale by 1/C and store ----
    const float sc = 1.0f / (float)NC;
    float* obase = out + (((size_t)b * (NP * NP) + (size_t)di * NP) * NH
                          + (i0 + ti)) * NW + jg * 8;
#pragma unroll
    for (int e = 0; e < 5; ++e) {
        float* op = obase + (size_t)(2 * e) * NH * NW;
        float4 v;
        upk(accE[e][0], v.x, v.y); upk(accE[e][1], v.z, v.w);
        v.x *= sc; v.y *= sc; v.z *= sc; v.w *= sc;
        *reinterpret_cast<float4*>(op) = v;
        upk(accE[e][2], v.x, v.y); upk(accE[e][3], v.z, v.w);
        v.x *= sc; v.y *= sc; v.z *= sc; v.w *= sc;
        *reinterpret_cast<float4*>(op + 4) = v;
    }
#pragma unroll
    for (int o = 0; o < 4; ++o) {
        float* op = obase + (size_t)(2 * o + 1) * NH * NW;
        float f1, f2, f3, f4, f5, f6;
        upk(accO[o][0], f1, f2);
        upk(accO[o][1], f3, f4);
        upk(accO[o][2], f5, f6);
        float4 v;
        v.x = sA[o] * sc; v.y = f1 * sc; v.z = f2 * sc; v.w = f3 * sc;
        *reinterpret_cast<float4*>(op) = v;
        v.x = f4 * sc; v.y = f5 * sc; v.z = f6 * sc; v.w = sB[o] * sc;
        *reinterpret_cast<float4*>(op + 4) = v;
    }
}

extern "C" void kernel_launch(void* const* d_in, const int* in_sizes, int n_in,
                              void* d_out, int out_size) {
    const float* x = (const float*)d_in[0];
    const float* y = (const float*)d_in[1];
    float* out = (float*)d_out;
    (void)in_sizes; (void)n_in; (void)out_size;

    cudaFuncSetAttribute(corr_kernel,
                         cudaFuncAttributeMaxDynamicSharedMemorySize, SMEM_TOTAL);

    dim3 grid(NH / TI, NB);   // (16, 16) = 256 blocks
    corr_kernel<<<grid, NTHREADS, SMEM_TOTAL>>>(x, y, out);
}